// round 3
// baseline (speedup 1.0000x reference)
#include <cuda_runtime.h>
#include <cstdint>
#include <cstddef>

// ---------------- configuration ----------------
#define TM 128
#define TN 32
#define TK 16
#define NTHR 256
#define MAXB 65536

// per-row coefficients: [set(x=0,y=1)][row][S1,S2,S3,S4]
__device__ float g_coef[2][MAXB][4];

// ---------------- Threefry-2x32-20 (exact JAX schedule) ----------------
__device__ __forceinline__ void threefry(uint32_t k0, uint32_t k1,
                                         uint32_t x0, uint32_t x1,
                                         uint32_t& o0, uint32_t& o1) {
    uint32_t ks2 = k0 ^ k1 ^ 0x1BD11BDAu;
    x0 += k0; x1 += k1;
#define TF_RND(r) { x0 += x1; x1 = (x1 << (r)) | (x1 >> (32 - (r))); x1 ^= x0; }
    TF_RND(13) TF_RND(15) TF_RND(26) TF_RND(6)
    x0 += k1;  x1 += ks2 + 1u;
    TF_RND(17) TF_RND(29) TF_RND(16) TF_RND(24)
    x0 += ks2; x1 += k0 + 2u;
    TF_RND(13) TF_RND(15) TF_RND(26) TF_RND(6)
    x0 += k0;  x1 += k1 + 3u;
    TF_RND(17) TF_RND(29) TF_RND(16) TF_RND(24)
    x0 += k1;  x1 += ks2 + 4u;
    TF_RND(13) TF_RND(15) TF_RND(26) TF_RND(6)
    x0 += ks2; x1 += k0 + 5u;
#undef TF_RND
    o0 = x0; o1 = x1;
}

// JAX uniform(0,1) from 32 random bits
__device__ __forceinline__ float bits_to_unit(uint32_t bits) {
    float f = __uint_as_float((bits >> 9) | 0x3f800000u) - 1.0f;
    return fmaxf(f, 0.0f);
}

// ---------------- fused GEMM + NLL coefficient reduction ----------------
// Block: TM rows x (loop over TN-col chunks), K = IN.
// blockIdx.y selects the x-set (0) or y-set (1).
__global__ __launch_bounds__(NTHR, 2)
void coef_kernel(const float* __restrict__ xin, const float* __restrict__ yin,
                 const float* __restrict__ Wmx, const float* __restrict__ bmx,
                 const float* __restrict__ Wsx, const float* __restrict__ bsx,
                 const float* __restrict__ Wmy, const float* __restrict__ bmy,
                 const float* __restrict__ Wsy, const float* __restrict__ bsy,
                 int B, int IN, int H)
{
    const int set = blockIdx.y;
    const float* __restrict__ A  = set ? yin : xin;
    const float* __restrict__ Wm = set ? Wmy : Wmx;
    const float* __restrict__ Ws = set ? Wsy : Wsx;
    const float* __restrict__ bm = set ? bmy : bmx;
    const float* __restrict__ bs = set ? bsy : bsx;
    const int r0 = blockIdx.x * TM;

    __shared__ float Xs[TK][TM];
    __shared__ float Wms[TK][TN];
    __shared__ float Wss[TK][TN];

    const int tid = threadIdx.x;
    const int tx = tid & 15;       // column group (2 cols)
    const int ty = tid >> 4;       // row group (8 rows)

    // A-tile load mapping: same row twice, k-quads {q, q+2}
    const int xr  = tid & 127;
    const int xk0 = (tid >> 7);          // 0 or 1
    const int xk1 = (tid >> 7) + 2;      // 2 or 3
    // W-tile load mapping
    const int wt  = tid & 127;
    const int wcol = wt & 31;
    const int wkq  = wt >> 5;            // 0..3
    const bool isMu = (tid < 128);

    float s1[8], s2[8], s3[8], s4[8];
#pragma unroll
    for (int r = 0; r < 8; r++) { s1[r] = 0.f; s2[r] = 0.f; s3[r] = 0.f; s4[r] = 0.f; }

    for (int nc = 0; nc < H; nc += TN) {
        float am[8][2], av[8][2];
#pragma unroll
        for (int r = 0; r < 8; r++) {
            am[r][0] = 0.f; am[r][1] = 0.f; av[r][0] = 0.f; av[r][1] = 0.f;
        }

        for (int k0 = 0; k0 < IN; k0 += TK) {
            // prefetch global tiles into registers
            float4 va0 = *(const float4*)(A + (size_t)(r0 + xr) * IN + k0 + xk0 * 4);
            float4 va1 = *(const float4*)(A + (size_t)(r0 + xr) * IN + k0 + xk1 * 4);
            const float* Wp = isMu ? Wm : Ws;
            float4 vw = *(const float4*)(Wp + (size_t)(nc + wcol) * IN + k0 + wkq * 4);

            __syncthreads();
            Xs[xk0*4 + 0][xr] = va0.x; Xs[xk0*4 + 1][xr] = va0.y;
            Xs[xk0*4 + 2][xr] = va0.z; Xs[xk0*4 + 3][xr] = va0.w;
            Xs[xk1*4 + 0][xr] = va1.x; Xs[xk1*4 + 1][xr] = va1.y;
            Xs[xk1*4 + 2][xr] = va1.z; Xs[xk1*4 + 3][xr] = va1.w;
            {
                float (*Wd)[TN] = isMu ? Wms : Wss;
                Wd[wkq*4 + 0][wcol] = vw.x; Wd[wkq*4 + 1][wcol] = vw.y;
                Wd[wkq*4 + 2][wcol] = vw.z; Wd[wkq*4 + 3][wcol] = vw.w;
            }
            __syncthreads();

#pragma unroll
            for (int k = 0; k < TK; k++) {
                float4 a0 = *(const float4*)&Xs[k][ty * 8];
                float4 a1 = *(const float4*)&Xs[k][ty * 8 + 4];
                float2 wmv = *(const float2*)&Wms[k][tx * 2];
                float2 wsv = *(const float2*)&Wss[k][tx * 2];
                float a[8] = {a0.x, a0.y, a0.z, a0.w, a1.x, a1.y, a1.z, a1.w};
#pragma unroll
                for (int r = 0; r < 8; r++) {
                    am[r][0] = fmaf(a[r], wmv.x, am[r][0]);
                    am[r][1] = fmaf(a[r], wmv.y, am[r][1]);
                    av[r][0] = fmaf(a[r], wsv.x, av[r][0]);
                    av[r][1] = fmaf(a[r], wsv.y, av[r][1]);
                }
            }
        }

        // epilogue: bias + exp + NLL partial sums
        float bmv0 = bm[nc + tx*2], bmv1 = bm[nc + tx*2 + 1];
        float bsv0 = bs[nc + tx*2], bsv1 = bs[nc + tx*2 + 1];
#pragma unroll
        for (int r = 0; r < 8; r++) {
#pragma unroll
            for (int c = 0; c < 2; c++) {
                float m = am[r][c] + (c ? bmv1 : bmv0);
                float v = expf(av[r][c] + (c ? bsv1 : bsv0));
                v = fmaxf(v, 1e-6f);           // GaussianNLLLoss eps clamp
                float lg = logf(v);
                float rc = 1.0f / v;
                s1[r] += lg;
                s2[r] += rc;
                s3[r] += m * rc;
                s4[r] += m * m * rc;
            }
        }
    }

    // reduce across the 16 tx lanes (same-row threads sit in 16-lane halves of a warp)
#pragma unroll
    for (int off = 1; off < 16; off <<= 1) {
#pragma unroll
        for (int r = 0; r < 8; r++) {
            s1[r] += __shfl_xor_sync(0xffffffffu, s1[r], off);
            s2[r] += __shfl_xor_sync(0xffffffffu, s2[r], off);
            s3[r] += __shfl_xor_sync(0xffffffffu, s3[r], off);
            s4[r] += __shfl_xor_sync(0xffffffffu, s4[r], off);
        }
    }
    if (tx == 0) {
#pragma unroll
        for (int r = 0; r < 8; r++) {
            int row = r0 + ty * 8 + r;
            if (row < B) {
                g_coef[set][row][0] = s1[r];
                g_coef[set][row][1] = s2[r];
                g_coef[set][row][2] = s3[r];
                g_coef[set][row][3] = s4[r];
            }
        }
    }
}

// ---------------- per-row rejection sampling (JAX threefry, partitionable mode) ----------------
__global__ void sample_kernel(float* __restrict__ out, int B, float invH)
{
    int i = blockIdx.x * blockDim.x + threadIdx.x;
    if (i >= B) return;

    float s1x = g_coef[0][i][0], s2x = g_coef[0][i][1];
    float s3x = g_coef[0][i][2], s4x = g_coef[0][i][3];
    float s1y = g_coef[1][i][0], s2y = g_coef[1][i][1];
    float s3y = g_coef[1][i][2], s4y = g_coef[1][i][3];

    // nll(xi) = a + b*xi + c*xi^2
    float ax = 0.5f * (s1x + s4x) * invH;
    float bxc = -s3x * invH;
    float cx = 0.5f * s2x * invH;
    float ay = 0.5f * (s1y + s4y) * invH;
    float byc = -s3y * invH;
    float cy = 0.5f * s2y * invH;

    // row key: split(key(42), B)[i] = threefry((0,42), (0, i))  [partitionable foldlike]
    uint32_t k0, k1;
    threefry(0u, 42u, 0u, (uint32_t)i, k0, k1);

    float xi = 0.0f;
    for (int it = 0; it < 4096; ++it) {
        // split(k, 3): new keys j=0,1,2 via threefry(k, (0, j))
        uint32_t n0, n1, p0, p1, q0, q1;
        threefry(k0, k1, 0u, 0u, n0, n1);   // next loop key
        threefry(k0, k1, 0u, 1u, p0, p1);   // k1 -> u
        threefry(k0, k1, 0u, 2u, q0, q1);   // k2 -> xi
        // scalar random_bits (partitionable): out0 ^ out1 of threefry(key, (0,0))
        uint32_t ub0, ub1, xb0, xb1;
        threefry(p0, p1, 0u, 0u, ub0, ub1);
        threefry(q0, q1, 0u, 0u, xb0, xb1);
        float u  = bits_to_unit(ub0 ^ ub1);
        float x2 = bits_to_unit(xb0 ^ xb1);
        xi = 2.0f * x2 - 1.0f;

        float qx = fmaf(fmaf(cx, xi, bxc), xi, ax);
        float qy = fmaf(fmaf(cy, xi, byc), xi, ay);
        float q  = qx * qy;

        k0 = n0; k1 = n1;
        if (u >= q) break;
    }
    out[i] = fminf(fmaxf(xi, 1e-5f), 10.0f);
}

// ---------------- launch ----------------
extern "C" void kernel_launch(void* const* d_in, const int* in_sizes, int n_in,
                              void* d_out, int out_size)
{
    const float* x   = (const float*)d_in[0];
    const float* y   = (const float*)d_in[1];
    const float* Wmx = (const float*)d_in[2];
    const float* bmx = (const float*)d_in[3];
    const float* Wsx = (const float*)d_in[4];
    const float* bsx = (const float*)d_in[5];
    const float* Wmy = (const float*)d_in[6];
    const float* bmy = (const float*)d_in[7];
    const float* Wsy = (const float*)d_in[8];
    const float* bsy = (const float*)d_in[9];

    int H  = in_sizes[3];
    int IN = in_sizes[2] / H;
    int B  = in_sizes[0] / IN;

    dim3 grid((B + TM - 1) / TM, 2);
    coef_kernel<<<grid, NTHR>>>(x, y, Wmx, bmx, Wsx, bsx, Wmy, bmy, Wsy, bsy, B, IN, H);

    int thr = 256;
    sample_kernel<<<(B + thr - 1) / thr, thr>>>((float*)d_out, B, 1.0f / (float)H);
}

// round 4
// speedup vs baseline: 1.1090x; 1.1090x over previous
#include <cuda_runtime.h>
#include <cstdint>
#include <cstddef>

// ---------------- configuration ----------------
#define TM 128
#define TN 32
#define TK 16
#define NTHR 256
#define MAXB 65536

// per-row coefficients: [set(x=0,y=1)][row][S1,S2,S3,S4]
__device__ float g_coef[2][MAXB][4];

// ---------------- packed f32x2 helpers ----------------
__device__ __forceinline__ void fma2(unsigned long long& acc,
                                     unsigned long long a,
                                     unsigned long long b) {
    asm("fma.rn.f32x2 %0, %1, %2, %0;" : "+l"(acc) : "l"(a), "l"(b));
}
__device__ __forceinline__ unsigned long long bcast2(float w) {
    unsigned long long r;
    asm("mov.b64 %0, {%1, %1};" : "=l"(r) : "f"(w));
    return r;
}
__device__ __forceinline__ void unpack2(unsigned long long v, float& lo, float& hi) {
    asm("mov.b64 {%0, %1}, %2;" : "=f"(lo), "=f"(hi) : "l"(v));
}

// ---------------- Threefry-2x32-20 (exact JAX schedule) ----------------
__device__ __forceinline__ void threefry(uint32_t k0, uint32_t k1,
                                         uint32_t x0, uint32_t x1,
                                         uint32_t& o0, uint32_t& o1) {
    uint32_t ks2 = k0 ^ k1 ^ 0x1BD11BDAu;
    x0 += k0; x1 += k1;
#define TF_RND(r) { x0 += x1; x1 = (x1 << (r)) | (x1 >> (32 - (r))); x1 ^= x0; }
    TF_RND(13) TF_RND(15) TF_RND(26) TF_RND(6)
    x0 += k1;  x1 += ks2 + 1u;
    TF_RND(17) TF_RND(29) TF_RND(16) TF_RND(24)
    x0 += ks2; x1 += k0 + 2u;
    TF_RND(13) TF_RND(15) TF_RND(26) TF_RND(6)
    x0 += k0;  x1 += k1 + 3u;
    TF_RND(17) TF_RND(29) TF_RND(16) TF_RND(24)
    x0 += k1;  x1 += ks2 + 4u;
    TF_RND(13) TF_RND(15) TF_RND(26) TF_RND(6)
    x0 += ks2; x1 += k0 + 5u;
#undef TF_RND
    o0 = x0; o1 = x1;
}

// JAX uniform(0,1) from 32 random bits
__device__ __forceinline__ float bits_to_unit(uint32_t bits) {
    float f = __uint_as_float((bits >> 9) | 0x3f800000u) - 1.0f;
    return fmaxf(f, 0.0f);
}

// ---------------- fused GEMM + NLL coefficient reduction ----------------
// Block: TM rows x (loop over TN-col chunks), K = IN.
// blockIdx.y selects the x-set (0) or y-set (1).
// Accumulators are packed f32x2 over ROW PAIRS -> FFMA2 (2x fp32 rate).
__global__ __launch_bounds__(NTHR, 2)
void coef_kernel(const float* __restrict__ xin, const float* __restrict__ yin,
                 const float* __restrict__ Wmx, const float* __restrict__ bmx,
                 const float* __restrict__ Wsx, const float* __restrict__ bsx,
                 const float* __restrict__ Wmy, const float* __restrict__ bmy,
                 const float* __restrict__ Wsy, const float* __restrict__ bsy,
                 int B, int IN, int H)
{
    const int set = blockIdx.y;
    const float* __restrict__ A  = set ? yin : xin;
    const float* __restrict__ Wm = set ? Wmy : Wmx;
    const float* __restrict__ Ws = set ? Wsy : Wsx;
    const float* __restrict__ bm = set ? bmy : bmx;
    const float* __restrict__ bs = set ? bsy : bsx;
    const int r0 = blockIdx.x * TM;

    __shared__ float Xs[TK][TM];
    __shared__ float Wms[TK][TN];
    __shared__ float Wss[TK][TN];

    const int tid = threadIdx.x;
    const int tx = tid & 15;       // column group (2 cols)
    const int ty = tid >> 4;       // row group (8 rows)

    // A-tile load mapping: same row twice, k-quads {q, q+2}
    const int xr  = tid & 127;
    const int xk0 = (tid >> 7);          // 0 or 1
    const int xk1 = (tid >> 7) + 2;      // 2 or 3
    // W-tile load mapping
    const int wt  = tid & 127;
    const int wcol = wt & 31;
    const int wkq  = wt >> 5;            // 0..3
    const bool isMu = (tid < 128);

    float s1[8], s2[8], s3[8], s4[8];
#pragma unroll
    for (int r = 0; r < 8; r++) { s1[r] = 0.f; s2[r] = 0.f; s3[r] = 0.f; s4[r] = 0.f; }

    for (int nc = 0; nc < H; nc += TN) {
        // packed accumulators: [row-pair p][col c], lanes = rows {2p, 2p+1}
        unsigned long long amP[4][2], avP[4][2];
#pragma unroll
        for (int p = 0; p < 4; p++) {
            amP[p][0] = 0ull; amP[p][1] = 0ull;
            avP[p][0] = 0ull; avP[p][1] = 0ull;
        }

        for (int k0 = 0; k0 < IN; k0 += TK) {
            // prefetch global tiles into registers
            float4 va0 = *(const float4*)(A + (size_t)(r0 + xr) * IN + k0 + xk0 * 4);
            float4 va1 = *(const float4*)(A + (size_t)(r0 + xr) * IN + k0 + xk1 * 4);
            const float* Wp = isMu ? Wm : Ws;
            float4 vw = *(const float4*)(Wp + (size_t)(nc + wcol) * IN + k0 + wkq * 4);

            __syncthreads();
            Xs[xk0*4 + 0][xr] = va0.x; Xs[xk0*4 + 1][xr] = va0.y;
            Xs[xk0*4 + 2][xr] = va0.z; Xs[xk0*4 + 3][xr] = va0.w;
            Xs[xk1*4 + 0][xr] = va1.x; Xs[xk1*4 + 1][xr] = va1.y;
            Xs[xk1*4 + 2][xr] = va1.z; Xs[xk1*4 + 3][xr] = va1.w;
            {
                float (*Wd)[TN] = isMu ? Wms : Wss;
                Wd[wkq*4 + 0][wcol] = vw.x; Wd[wkq*4 + 1][wcol] = vw.y;
                Wd[wkq*4 + 2][wcol] = vw.z; Wd[wkq*4 + 3][wcol] = vw.w;
            }
            __syncthreads();

#pragma unroll
            for (int k = 0; k < TK; k++) {
                // row pairs load directly as 64-bit lanes (no pack instructions)
                ulonglong2 A0 = *(const ulonglong2*)&Xs[k][ty * 8];
                ulonglong2 A1 = *(const ulonglong2*)&Xs[k][ty * 8 + 4];
                float2 wmv = *(const float2*)&Wms[k][tx * 2];
                float2 wsv = *(const float2*)&Wss[k][tx * 2];
                unsigned long long wm0 = bcast2(wmv.x);
                unsigned long long wm1 = bcast2(wmv.y);
                unsigned long long ws0 = bcast2(wsv.x);
                unsigned long long ws1 = bcast2(wsv.y);
                unsigned long long ap[4] = {A0.x, A0.y, A1.x, A1.y};
#pragma unroll
                for (int p = 0; p < 4; p++) {
                    fma2(amP[p][0], ap[p], wm0);
                    fma2(amP[p][1], ap[p], wm1);
                    fma2(avP[p][0], ap[p], ws0);
                    fma2(avP[p][1], ap[p], ws1);
                }
            }
        }

        // epilogue: bias + exp + NLL partial sums (identical math/order to scalar version)
        float bmv0 = bm[nc + tx*2], bmv1 = bm[nc + tx*2 + 1];
        float bsv0 = bs[nc + tx*2], bsv1 = bs[nc + tx*2 + 1];
#pragma unroll
        for (int p = 0; p < 4; p++) {
#pragma unroll
            for (int c = 0; c < 2; c++) {
                float mlo, mhi, vlo, vhi;
                unpack2(amP[p][c], mlo, mhi);
                unpack2(avP[p][c], vlo, vhi);
                float am2[2] = {mlo, mhi};
                float av2[2] = {vlo, vhi};
#pragma unroll
                for (int h = 0; h < 2; h++) {
                    int r = 2 * p + h;
                    float m = am2[h] + (c ? bmv1 : bmv0);
                    float v = expf(av2[h] + (c ? bsv1 : bsv0));
                    v = fmaxf(v, 1e-6f);           // GaussianNLLLoss eps clamp
                    float lg = logf(v);
                    float rc = 1.0f / v;
                    s1[r] += lg;
                    s2[r] += rc;
                    s3[r] += m * rc;
                    s4[r] += m * m * rc;
                }
            }
        }
    }

    // reduce across the 16 tx lanes (same-row threads sit in 16-lane halves of a warp)
#pragma unroll
    for (int off = 1; off < 16; off <<= 1) {
#pragma unroll
        for (int r = 0; r < 8; r++) {
            s1[r] += __shfl_xor_sync(0xffffffffu, s1[r], off);
            s2[r] += __shfl_xor_sync(0xffffffffu, s2[r], off);
            s3[r] += __shfl_xor_sync(0xffffffffu, s3[r], off);
            s4[r] += __shfl_xor_sync(0xffffffffu, s4[r], off);
        }
    }
    if (tx == 0) {
#pragma unroll
        for (int r = 0; r < 8; r++) {
            int row = r0 + ty * 8 + r;
            if (row < B) {
                g_coef[set][row][0] = s1[r];
                g_coef[set][row][1] = s2[r];
                g_coef[set][row][2] = s3[r];
                g_coef[set][row][3] = s4[r];
            }
        }
    }
}

// ---------------- per-row rejection sampling (JAX threefry, partitionable mode) ----------------
__global__ void sample_kernel(float* __restrict__ out, int B, float invH)
{
    int i = blockIdx.x * blockDim.x + threadIdx.x;
    if (i >= B) return;

    float s1x = g_coef[0][i][0], s2x = g_coef[0][i][1];
    float s3x = g_coef[0][i][2], s4x = g_coef[0][i][3];
    float s1y = g_coef[1][i][0], s2y = g_coef[1][i][1];
    float s3y = g_coef[1][i][2], s4y = g_coef[1][i][3];

    // nll(xi) = a + b*xi + c*xi^2
    float ax = 0.5f * (s1x + s4x) * invH;
    float bxc = -s3x * invH;
    float cx = 0.5f * s2x * invH;
    float ay = 0.5f * (s1y + s4y) * invH;
    float byc = -s3y * invH;
    float cy = 0.5f * s2y * invH;

    // row key: split(key(42), B)[i] = threefry((0,42), (0, i))  [partitionable foldlike]
    uint32_t k0, k1;
    threefry(0u, 42u, 0u, (uint32_t)i, k0, k1);

    float xi = 0.0f;
    for (int it = 0; it < 4096; ++it) {
        // split(k, 3): new keys j=0,1,2 via threefry(k, (0, j))
        uint32_t n0, n1, p0, p1, q0, q1;
        threefry(k0, k1, 0u, 0u, n0, n1);   // next loop key
        threefry(k0, k1, 0u, 1u, p0, p1);   // k1 -> u
        threefry(k0, k1, 0u, 2u, q0, q1);   // k2 -> xi
        // scalar random_bits (partitionable): out0 ^ out1 of threefry(key, (0,0))
        uint32_t ub0, ub1, xb0, xb1;
        threefry(p0, p1, 0u, 0u, ub0, ub1);
        threefry(q0, q1, 0u, 0u, xb0, xb1);
        float u  = bits_to_unit(ub0 ^ ub1);
        float x2 = bits_to_unit(xb0 ^ xb1);
        xi = 2.0f * x2 - 1.0f;

        float qx = fmaf(fmaf(cx, xi, bxc), xi, ax);
        float qy = fmaf(fmaf(cy, xi, byc), xi, ay);
        float q  = qx * qy;

        k0 = n0; k1 = n1;
        if (u >= q) break;
    }
    out[i] = fminf(fmaxf(xi, 1e-5f), 10.0f);
}

// ---------------- launch ----------------
extern "C" void kernel_launch(void* const* d_in, const int* in_sizes, int n_in,
                              void* d_out, int out_size)
{
    const float* x   = (const float*)d_in[0];
    const float* y   = (const float*)d_in[1];
    const float* Wmx = (const float*)d_in[2];
    const float* bmx = (const float*)d_in[3];
    const float* Wsx = (const float*)d_in[4];
    const float* bsx = (const float*)d_in[5];
    const float* Wmy = (const float*)d_in[6];
    const float* bmy = (const float*)d_in[7];
    const float* Wsy = (const float*)d_in[8];
    const float* bsy = (const float*)d_in[9];

    int H  = in_sizes[3];
    int IN = in_sizes[2] / H;
    int B  = in_sizes[0] / IN;

    dim3 grid((B + TM - 1) / TM, 2);
    coef_kernel<<<grid, NTHR>>>(x, y, Wmx, bmx, Wsx, bsx, Wmy, bmy, Wsy, bsy, B, IN, H);

    int thr = 256;
    sample_kernel<<<(B + thr - 1) / thr, thr>>>((float*)d_out, B, 1.0f / (float)H);
}

// round 6
// speedup vs baseline: 1.2042x; 1.0858x over previous
#include <cuda_runtime.h>
#include <cstdint>
#include <cstddef>

// ---------------- configuration ----------------
#define MAXB  65536
#define MT    128           // CTA rows
#define NT    64            // CTA cols per chunk
#define KB    32            // k-block (floats)
#define KPAD  36            // padded floats per smem row (bank-conflict-free)
#define ROWB  (KPAD * 4)    // 144 bytes
#define SA_BYTES (MT * ROWB)          // 18432
#define SW_BYTES (4 * NT * ROWB)      // 36864 (Wmh,Wml,Wsh,Wsl tiles)
#define STAGE_BYTES (SA_BYTES + SW_BYTES)   // 55296
#define SM_BIAS 0
#define SM_RED  4096
#define SM_TILE 8192
#define SMEM_TOTAL (SM_TILE + 2 * STAGE_BYTES)  // 118784

// per-row coefficients: [set(x=0,y=1)][row][S1,S2,S3,S4]
__device__ float g_coef[2][MAXB][4];
// tf32 split weights: [set][mu=0,sg=1]
__device__ float g_Wh[2][2][512 * 512];
__device__ float g_Wl[2][2][512 * 512];

// ---------------- helpers ----------------
__device__ __forceinline__ float tf32_of(float a) {
    uint32_t u;
    asm("cvt.rna.tf32.f32 %0, %1;" : "=r"(u) : "f"(a));
    return __uint_as_float(u);
}
__device__ __forceinline__ void tf32split(float a, uint32_t& hb, uint32_t& lb) {
    uint32_t h;
    asm("cvt.rna.tf32.f32 %0, %1;" : "=r"(h) : "f"(a));
    float hf = __uint_as_float(h);
    uint32_t l;
    asm("cvt.rna.tf32.f32 %0, %1;" : "=r"(l) : "f"(a - hf));
    hb = h; lb = l;
}
__device__ __forceinline__ void cpa16(uint32_t dst, const void* src) {
    asm volatile("cp.async.cg.shared.global [%0], [%1], 16;" :: "r"(dst), "l"(src));
}
__device__ __forceinline__ uint32_t smem_u32(const void* p) {
    uint32_t a;
    asm("{ .reg .u64 t; cvta.to.shared.u64 t, %1; cvt.u32.u64 %0, t; }" : "=r"(a) : "l"(p));
    return a;
}
__device__ __forceinline__ void mma_tf32(float* d, const uint32_t* a, const uint32_t* b) {
    asm volatile(
        "mma.sync.aligned.m16n8k8.row.col.f32.tf32.tf32.f32 "
        "{%0,%1,%2,%3}, {%4,%5,%6,%7}, {%8,%9}, {%0,%1,%2,%3};"
        : "+f"(d[0]), "+f"(d[1]), "+f"(d[2]), "+f"(d[3])
        : "r"(a[0]), "r"(a[1]), "r"(a[2]), "r"(a[3]), "r"(b[0]), "r"(b[1]));
}

// ---------------- prep: tf32 hi/lo split of weights ----------------
__global__ void split_w_kernel(const float* __restrict__ src, int set, int mat, int n4) {
    int i = blockIdx.x * blockDim.x + threadIdx.x;
    if (i >= n4) return;
    float4 a = ((const float4*)src)[i];
    float4 h, l;
    h.x = tf32_of(a.x); l.x = tf32_of(a.x - h.x);
    h.y = tf32_of(a.y); l.y = tf32_of(a.y - h.y);
    h.z = tf32_of(a.z); l.z = tf32_of(a.z - h.z);
    h.w = tf32_of(a.w); l.w = tf32_of(a.w - h.w);
    ((float4*)g_Wh[set][mat])[i] = h;
    ((float4*)g_Wl[set][mat])[i] = l;
}

// ---------------- fused 3xTF32 mma GEMM + NLL coefficient kernel ----------------
// grid = (B/MT, 2); 256 threads = 8 warps as 4(M) x 2(N); warp tile 32x32.
struct WSrc { const float* p[4]; };

__device__ __forceinline__ void issue_loads(uint32_t base, const float* __restrict__ A,
                                            const WSrc& W, int r0, int n0, int kb,
                                            int IN, int tid)
{
    // A tile: 128 rows x 8 chunks (16B)
#pragma unroll
    for (int it = 0; it < 4; ++it) {
        int t = tid + it * 256;
        int r = t >> 3, c = t & 7;
        cpa16(base + r * ROWB + c * 16, A + (size_t)(r0 + r) * IN + kb + c * 4);
    }
    // W tiles: 4 x (64 rows x 8 chunks)
#pragma unroll
    for (int it = 0; it < 8; ++it) {
        int tt = it >> 1;
        int u = (tid + it * 256) & 511;
        int r = u >> 3, c = u & 7;
        cpa16(base + SA_BYTES + tt * (NT * ROWB) + r * ROWB + c * 16,
              W.p[tt] + (size_t)(n0 + r) * IN + kb + c * 4);
    }
    asm volatile("cp.async.commit_group;" ::: "memory");
}

__global__ __launch_bounds__(256, 1)
void coef_mma_kernel(const float* __restrict__ xin, const float* __restrict__ yin,
                     const float* __restrict__ bmx, const float* __restrict__ bsx,
                     const float* __restrict__ bmy, const float* __restrict__ bsy,
                     int B, int IN, int H)
{
    extern __shared__ char smem[];
    const int set  = blockIdx.y;
    const int r0   = blockIdx.x * MT;
    const int tid  = threadIdx.x;
    const int wid  = tid >> 5;
    const int lane = tid & 31;
    const int wm   = wid & 3;       // M stripe (32 rows)
    const int wn   = wid >> 2;      // N stripe (32 cols)
    const int g    = lane >> 2;     // group id
    const int tg   = lane & 3;      // thread in group
    const uint32_t sb = smem_u32(smem);

    const float* __restrict__ A = set ? yin : xin;
    WSrc W;
    W.p[0] = g_Wh[set][0];  // Wm hi
    W.p[1] = g_Wl[set][0];  // Wm lo
    W.p[2] = g_Wh[set][1];  // Ws hi
    W.p[3] = g_Wl[set][1];  // Ws lo

    // bias preload: [0,H) mu, [H,2H) sg
    {
        const float* bmu = set ? bmy : bmx;
        const float* bsg = set ? bsy : bsx;
        float* bias_s = (float*)(smem + SM_BIAS);
        for (int t = tid; t < H; t += 256) { bias_s[t] = bmu[t]; bias_s[H + t] = bsg[t]; }
    }
    __syncthreads();
    const float* bias_s = (const float*)(smem + SM_BIAS);

    float s1[4] = {0.f, 0.f, 0.f, 0.f};
    float s2[4] = {0.f, 0.f, 0.f, 0.f};
    float s3[4] = {0.f, 0.f, 0.f, 0.f};
    float s4[4] = {0.f, 0.f, 0.f, 0.f};

    const int nkc = IN / KB;   // 16
    const int nnh = H / NT;    // 8

    for (int nh = 0; nh < nnh; ++nh) {
        const int n0 = nh * NT;
        float accMu[2][4][4], accSg[2][4][4];
#pragma unroll
        for (int i = 0; i < 2; ++i)
#pragma unroll
            for (int j = 0; j < 4; ++j)
#pragma unroll
                for (int c = 0; c < 4; ++c) { accMu[i][j][c] = 0.f; accSg[i][j][c] = 0.f; }

        issue_loads(sb + SM_TILE, A, W, r0, n0, 0, IN, tid);

        for (int kc = 0; kc < nkc; ++kc) {
            if (kc + 1 < nkc) {
                issue_loads(sb + SM_TILE + ((kc + 1) & 1) * STAGE_BYTES,
                            A, W, r0, n0, (kc + 1) * KB, IN, tid);
                asm volatile("cp.async.wait_group 1;" ::: "memory");
            } else {
                asm volatile("cp.async.wait_group 0;" ::: "memory");
            }
            __syncthreads();

            const uint32_t* At = (const uint32_t*)(smem + SM_TILE + (kc & 1) * STAGE_BYTES);
            const uint32_t* Wt = At + SA_BYTES / 4;

#pragma unroll
            for (int ks = 0; ks < KB / 8; ++ks) {
                const int kk = ks * 8 + tg;
                // A fragments (fp32 -> tf32 hi/lo split in registers)
                uint32_t ah[2][4], al[2][4];
#pragma unroll
                for (int i = 0; i < 2; ++i) {
                    int mr = wm * 32 + i * 16 + g;
                    float a0 = __uint_as_float(At[mr * KPAD + kk]);
                    float a1 = __uint_as_float(At[(mr + 8) * KPAD + kk]);
                    float a2 = __uint_as_float(At[mr * KPAD + kk + 4]);
                    float a3 = __uint_as_float(At[(mr + 8) * KPAD + kk + 4]);
                    tf32split(a0, ah[i][0], al[i][0]);
                    tf32split(a1, ah[i][1], al[i][1]);
                    tf32split(a2, ah[i][2], al[i][2]);
                    tf32split(a3, ah[i][3], al[i][3]);
                }
#pragma unroll
                for (int j = 0; j < 4; ++j) {
                    int nr = wn * 32 + j * 8 + g;
                    int o  = nr * KPAD + kk;
                    uint32_t bmh[2] = { Wt[0 * NT * KPAD + o], Wt[0 * NT * KPAD + o + 4] };
                    uint32_t bml[2] = { Wt[1 * NT * KPAD + o], Wt[1 * NT * KPAD + o + 4] };
                    uint32_t bsh[2] = { Wt[2 * NT * KPAD + o], Wt[2 * NT * KPAD + o + 4] };
                    uint32_t bsl[2] = { Wt[3 * NT * KPAD + o], Wt[3 * NT * KPAD + o + 4] };
#pragma unroll
                    for (int i = 0; i < 2; ++i) {
                        mma_tf32(accMu[i][j], ah[i], bmh);
                        mma_tf32(accMu[i][j], ah[i], bml);
                        mma_tf32(accMu[i][j], al[i], bmh);
                        mma_tf32(accSg[i][j], ah[i], bsh);
                        mma_tf32(accSg[i][j], ah[i], bsl);
                        mma_tf32(accSg[i][j], al[i], bsh);
                    }
                }
            }
            __syncthreads();
        }

        // epilogue: bias + exp/log/rcp + NLL partial sums
#pragma unroll
        for (int i = 0; i < 2; ++i) {
#pragma unroll
            for (int j = 0; j < 4; ++j) {
#pragma unroll
                for (int c = 0; c < 4; ++c) {
                    int h = n0 + wn * 32 + j * 8 + 2 * tg + (c & 1);
                    float m = accMu[i][j][c] + bias_s[h];
                    float v = expf(accSg[i][j][c] + bias_s[H + h]);
                    v = fmaxf(v, 1e-6f);        // GaussianNLLLoss eps clamp
                    float lg = logf(v);
                    float rc = 1.0f / v;
                    int slot = i * 2 + (c >> 1);
                    s1[slot] += lg;
                    s2[slot] += rc;
                    s3[slot] += m * rc;
                    s4[slot] += m * m * rc;
                }
            }
        }
    }

    // reduce over the 4 lanes of each group (cols), then across the 2 N-warps
#pragma unroll
    for (int slot = 0; slot < 4; ++slot) {
        s1[slot] += __shfl_xor_sync(0xffffffffu, s1[slot], 1);
        s1[slot] += __shfl_xor_sync(0xffffffffu, s1[slot], 2);
        s2[slot] += __shfl_xor_sync(0xffffffffu, s2[slot], 1);
        s2[slot] += __shfl_xor_sync(0xffffffffu, s2[slot], 2);
        s3[slot] += __shfl_xor_sync(0xffffffffu, s3[slot], 1);
        s3[slot] += __shfl_xor_sync(0xffffffffu, s3[slot], 2);
        s4[slot] += __shfl_xor_sync(0xffffffffu, s4[slot], 1);
        s4[slot] += __shfl_xor_sync(0xffffffffu, s4[slot], 2);
    }
    float (*red)[4] = (float(*)[4])(smem + SM_RED);
    __syncthreads();
    if (wn == 0 && tg == 0) {
#pragma unroll
        for (int slot = 0; slot < 4; ++slot) {
            int row = wm * 32 + (slot >> 1) * 16 + (slot & 1) * 8 + g;
            red[row][0] = s1[slot]; red[row][1] = s2[slot];
            red[row][2] = s3[slot]; red[row][3] = s4[slot];
        }
    }
    __syncthreads();
    if (wn == 1 && tg == 0) {
#pragma unroll
        for (int slot = 0; slot < 4; ++slot) {
            int row = wm * 32 + (slot >> 1) * 16 + (slot & 1) * 8 + g;
            int grow = r0 + row;
            if (grow < B) {
                g_coef[set][grow][0] = red[row][0] + s1[slot];
                g_coef[set][grow][1] = red[row][1] + s2[slot];
                g_coef[set][grow][2] = red[row][2] + s3[slot];
                g_coef[set][grow][3] = red[row][3] + s4[slot];
            }
        }
    }
}

// ---------------- Threefry-2x32-20 (exact JAX schedule) ----------------
__device__ __forceinline__ void threefry(uint32_t k0, uint32_t k1,
                                         uint32_t x0, uint32_t x1,
                                         uint32_t& o0, uint32_t& o1) {
    uint32_t ks2 = k0 ^ k1 ^ 0x1BD11BDAu;
    x0 += k0; x1 += k1;
#define TF_RND(r) { x0 += x1; x1 = (x1 << (r)) | (x1 >> (32 - (r))); x1 ^= x0; }
    TF_RND(13) TF_RND(15) TF_RND(26) TF_RND(6)
    x0 += k1;  x1 += ks2 + 1u;
    TF_RND(17) TF_RND(29) TF_RND(16) TF_RND(24)
    x0 += ks2; x1 += k0 + 2u;
    TF_RND(13) TF_RND(15) TF_RND(26) TF_RND(6)
    x0 += k0;  x1 += k1 + 3u;
    TF_RND(17) TF_RND(29) TF_RND(16) TF_RND(24)
    x0 += k1;  x1 += ks2 + 4u;
    TF_RND(13) TF_RND(15) TF_RND(26) TF_RND(6)
    x0 += ks2; x1 += k0 + 5u;
#undef TF_RND
    o0 = x0; o1 = x1;
}

__device__ __forceinline__ float bits_to_unit(uint32_t bits) {
    float f = __uint_as_float((bits >> 9) | 0x3f800000u) - 1.0f;
    return fmaxf(f, 0.0f);
}

// ---------------- per-row rejection sampling (JAX threefry, partitionable mode) ----------------
__global__ void sample_kernel(float* __restrict__ out, int B, float invH)
{
    int i = blockIdx.x * blockDim.x + threadIdx.x;
    if (i >= B) return;

    float s1x = g_coef[0][i][0], s2x = g_coef[0][i][1];
    float s3x = g_coef[0][i][2], s4x = g_coef[0][i][3];
    float s1y = g_coef[1][i][0], s2y = g_coef[1][i][1];
    float s3y = g_coef[1][i][2], s4y = g_coef[1][i][3];

    float ax = 0.5f * (s1x + s4x) * invH;
    float bxc = -s3x * invH;
    float cx = 0.5f * s2x * invH;
    float ay = 0.5f * (s1y + s4y) * invH;
    float byc = -s3y * invH;
    float cy = 0.5f * s2y * invH;

    uint32_t k0, k1;
    threefry(0u, 42u, 0u, (uint32_t)i, k0, k1);

    float xi = 0.0f;
    for (int it = 0; it < 4096; ++it) {
        uint32_t n0, n1, p0, p1, q0, q1;
        threefry(k0, k1, 0u, 0u, n0, n1);
        threefry(k0, k1, 0u, 1u, p0, p1);
        threefry(k0, k1, 0u, 2u, q0, q1);
        uint32_t ub0, ub1, xb0, xb1;
        threefry(p0, p1, 0u, 0u, ub0, ub1);
        threefry(q0, q1, 0u, 0u, xb0, xb1);
        float u  = bits_to_unit(ub0 ^ ub1);
        float x2 = bits_to_unit(xb0 ^ xb1);
        xi = 2.0f * x2 - 1.0f;

        float qx = fmaf(fmaf(cx, xi, bxc), xi, ax);
        float qy = fmaf(fmaf(cy, xi, byc), xi, ay);
        float q  = qx * qy;

        k0 = n0; k1 = n1;
        if (u >= q) break;
    }
    out[i] = fminf(fmaxf(xi, 1e-5f), 10.0f);
}

// ---------------- launch ----------------
extern "C" void kernel_launch(void* const* d_in, const int* in_sizes, int n_in,
                              void* d_out, int out_size)
{
    const float* x   = (const float*)d_in[0];
    const float* y   = (const float*)d_in[1];
    const float* Wmx = (const float*)d_in[2];
    const float* bmx = (const float*)d_in[3];
    const float* Wsx = (const float*)d_in[4];
    const float* bsx = (const float*)d_in[5];
    const float* Wmy = (const float*)d_in[6];
    const float* bmy = (const float*)d_in[7];
    const float* Wsy = (const float*)d_in[8];
    const float* bsy = (const float*)d_in[9];

    int H  = in_sizes[3];
    int IN = in_sizes[2] / H;
    int B  = in_sizes[0] / IN;

    int w4 = (H * IN) / 4;
    split_w_kernel<<<(w4 + 255) / 256, 256>>>(Wmx, 0, 0, w4);
    split_w_kernel<<<(w4 + 255) / 256, 256>>>(Wsx, 0, 1, w4);
    split_w_kernel<<<(w4 + 255) / 256, 256>>>(Wmy, 1, 0, w4);
    split_w_kernel<<<(w4 + 255) / 256, 256>>>(Wsy, 1, 1, w4);

    cudaFuncSetAttribute(coef_mma_kernel, cudaFuncAttributeMaxDynamicSharedMemorySize, SMEM_TOTAL);
    dim3 grid(B / MT, 2);
    coef_mma_kernel<<<grid, 256, SMEM_TOTAL>>>(x, y, bmx, bsx, bmy, bsy, B, IN, H);

    int thr = 256;
    sample_kernel<<<(B + thr - 1) / thr, thr>>>((float*)d_out, B, 1.0f / (float)H);
}

// round 7
// speedup vs baseline: 1.8657x; 1.5493x over previous
#include <cuda_runtime.h>
#include <cstdint>
#include <cstddef>

// ---------------- configuration ----------------
#define MAXB  65536
#define MT    128           // CTA rows
#define NT    64            // CTA cols per chunk
#define KB    32            // k-block (floats)
#define KPAD  36            // padded floats per smem row (bank-conflict-free)
#define ROWB  (KPAD * 4)    // 144 bytes
#define SA_BYTES (MT * ROWB)          // 18432
#define SW_BYTES (4 * NT * ROWB)      // 36864 (Wmh,Wml,Wsh,Wsl tiles)
#define STAGE_BYTES (SA_BYTES + SW_BYTES)   // 55296
#define SM_BIAS 0
#define SM_RED  4096
#define SM_TILE 8192
#define SMEM_TOTAL (SM_TILE + 2 * STAGE_BYTES)  // 118784

// per-row coefficients: [set(x=0,y=1)][row][S1,S2,S3,S4]
__device__ float g_coef[2][MAXB][4];
// tf32 split weights: [set][mu=0,sg=1]
__device__ float g_Wh[2][2][512 * 512];
__device__ float g_Wl[2][2][512 * 512];

// ---------------- helpers ----------------
__device__ __forceinline__ float tf32_of(float a) {
    uint32_t u;
    asm("cvt.rna.tf32.f32 %0, %1;" : "=r"(u) : "f"(a));
    return __uint_as_float(u);
}
__device__ __forceinline__ void tf32split(float a, uint32_t& hb, uint32_t& lb) {
    uint32_t h;
    asm("cvt.rna.tf32.f32 %0, %1;" : "=r"(h) : "f"(a));
    float hf = __uint_as_float(h);
    uint32_t l;
    asm("cvt.rna.tf32.f32 %0, %1;" : "=r"(l) : "f"(a - hf));
    hb = h; lb = l;
}
__device__ __forceinline__ void cpa16(uint32_t dst, const void* src) {
    asm volatile("cp.async.cg.shared.global [%0], [%1], 16;" :: "r"(dst), "l"(src));
}
__device__ __forceinline__ uint32_t smem_u32(const void* p) {
    uint32_t a;
    asm("{ .reg .u64 t; cvta.to.shared.u64 t, %1; cvt.u32.u64 %0, t; }" : "=r"(a) : "l"(p));
    return a;
}
__device__ __forceinline__ void mma_tf32(float* d, const uint32_t* a, const uint32_t* b) {
    asm volatile(
        "mma.sync.aligned.m16n8k8.row.col.f32.tf32.tf32.f32 "
        "{%0,%1,%2,%3}, {%4,%5,%6,%7}, {%8,%9}, {%0,%1,%2,%3};"
        : "+f"(d[0]), "+f"(d[1]), "+f"(d[2]), "+f"(d[3])
        : "r"(a[0]), "r"(a[1]), "r"(a[2]), "r"(a[3]), "r"(b[0]), "r"(b[1]));
}

// ---------------- prep: tf32 hi/lo split of weights ----------------
__global__ void split_w_kernel(const float* __restrict__ src, int set, int mat, int n4) {
    int i = blockIdx.x * blockDim.x + threadIdx.x;
    if (i >= n4) return;
    float4 a = ((const float4*)src)[i];
    float4 h, l;
    h.x = tf32_of(a.x); l.x = tf32_of(a.x - h.x);
    h.y = tf32_of(a.y); l.y = tf32_of(a.y - h.y);
    h.z = tf32_of(a.z); l.z = tf32_of(a.z - h.z);
    h.w = tf32_of(a.w); l.w = tf32_of(a.w - h.w);
    ((float4*)g_Wh[set][mat])[i] = h;
    ((float4*)g_Wl[set][mat])[i] = l;
}

// ---------------- fused 3xTF32 mma GEMM + NLL coefficient kernel ----------------
// grid = (B/MT, 2); 256 threads = 8 warps as 4(M) x 2(N); warp tile 32x32.
struct WSrc { const float* p[4]; };

__device__ __forceinline__ void issue_loads(uint32_t base, const float* __restrict__ A,
                                            const WSrc& W, int r0, int n0, int kb,
                                            int IN, int tid)
{
    // A tile: 128 rows x 8 chunks (16B)
#pragma unroll
    for (int it = 0; it < 4; ++it) {
        int t = tid + it * 256;
        int r = t >> 3, c = t & 7;
        cpa16(base + r * ROWB + c * 16, A + (size_t)(r0 + r) * IN + kb + c * 4);
    }
    // W tiles: 4 x (64 rows x 8 chunks)
#pragma unroll
    for (int it = 0; it < 8; ++it) {
        int tt = it >> 1;
        int u = (tid + it * 256) & 511;
        int r = u >> 3, c = u & 7;
        cpa16(base + SA_BYTES + tt * (NT * ROWB) + r * ROWB + c * 16,
              W.p[tt] + (size_t)(n0 + r) * IN + kb + c * 4);
    }
    asm volatile("cp.async.commit_group;" ::: "memory");
}

__global__ __launch_bounds__(256, 1)
void coef_mma_kernel(const float* __restrict__ xin, const float* __restrict__ yin,
                     const float* __restrict__ bmx, const float* __restrict__ bsx,
                     const float* __restrict__ bmy, const float* __restrict__ bsy,
                     int B, int IN, int H)
{
    extern __shared__ char smem[];
    const int set  = blockIdx.y;
    const int r0   = blockIdx.x * MT;
    const int tid  = threadIdx.x;
    const int wid  = tid >> 5;
    const int lane = tid & 31;
    const int wm   = wid & 3;       // M stripe (32 rows)
    const int wn   = wid >> 2;      // N stripe (32 cols)
    const int g    = lane >> 2;     // group id
    const int tg   = lane & 3;      // thread in group
    const uint32_t sb = smem_u32(smem);

    const float* __restrict__ A = set ? yin : xin;
    WSrc W;
    W.p[0] = g_Wh[set][0];  // Wm hi
    W.p[1] = g_Wl[set][0];  // Wm lo
    W.p[2] = g_Wh[set][1];  // Ws hi
    W.p[3] = g_Wl[set][1];  // Ws lo

    // bias preload: [0,H) mu, [H,2H) sg
    {
        const float* bmu = set ? bmy : bmx;
        const float* bsg = set ? bsy : bsx;
        float* bias_s = (float*)(smem + SM_BIAS);
        for (int t = tid; t < H; t += 256) { bias_s[t] = bmu[t]; bias_s[H + t] = bsg[t]; }
    }
    __syncthreads();
    const float* bias_s = (const float*)(smem + SM_BIAS);

    float s1[4] = {0.f, 0.f, 0.f, 0.f};
    float s2[4] = {0.f, 0.f, 0.f, 0.f};
    float s3[4] = {0.f, 0.f, 0.f, 0.f};
    float s4[4] = {0.f, 0.f, 0.f, 0.f};

    const int nkc = IN / KB;   // 16
    const int nnh = H / NT;    // 8

    for (int nh = 0; nh < nnh; ++nh) {
        const int n0 = nh * NT;
        float accMu[2][4][4], accSg[2][4][4];
#pragma unroll
        for (int i = 0; i < 2; ++i)
#pragma unroll
            for (int j = 0; j < 4; ++j)
#pragma unroll
                for (int c = 0; c < 4; ++c) { accMu[i][j][c] = 0.f; accSg[i][j][c] = 0.f; }

        issue_loads(sb + SM_TILE, A, W, r0, n0, 0, IN, tid);

        for (int kc = 0; kc < nkc; ++kc) {
            if (kc + 1 < nkc) {
                issue_loads(sb + SM_TILE + ((kc + 1) & 1) * STAGE_BYTES,
                            A, W, r0, n0, (kc + 1) * KB, IN, tid);
                asm volatile("cp.async.wait_group 1;" ::: "memory");
            } else {
                asm volatile("cp.async.wait_group 0;" ::: "memory");
            }
            __syncthreads();

            const uint32_t* At = (const uint32_t*)(smem + SM_TILE + (kc & 1) * STAGE_BYTES);
            const uint32_t* Wt = At + SA_BYTES / 4;

#pragma unroll
            for (int ks = 0; ks < KB / 8; ++ks) {
                const int kk = ks * 8 + tg;
                // A fragments (fp32 -> tf32 hi/lo split in registers)
                uint32_t ah[2][4], al[2][4];
#pragma unroll
                for (int i = 0; i < 2; ++i) {
                    int mr = wm * 32 + i * 16 + g;
                    float a0 = __uint_as_float(At[mr * KPAD + kk]);
                    float a1 = __uint_as_float(At[(mr + 8) * KPAD + kk]);
                    float a2 = __uint_as_float(At[mr * KPAD + kk + 4]);
                    float a3 = __uint_as_float(At[(mr + 8) * KPAD + kk + 4]);
                    tf32split(a0, ah[i][0], al[i][0]);
                    tf32split(a1, ah[i][1], al[i][1]);
                    tf32split(a2, ah[i][2], al[i][2]);
                    tf32split(a3, ah[i][3], al[i][3]);
                }
#pragma unroll
                for (int j = 0; j < 4; ++j) {
                    int nr = wn * 32 + j * 8 + g;
                    int o  = nr * KPAD + kk;
                    uint32_t bmh[2] = { Wt[0 * NT * KPAD + o], Wt[0 * NT * KPAD + o + 4] };
                    uint32_t bml[2] = { Wt[1 * NT * KPAD + o], Wt[1 * NT * KPAD + o + 4] };
                    uint32_t bsh[2] = { Wt[2 * NT * KPAD + o], Wt[2 * NT * KPAD + o + 4] };
                    uint32_t bsl[2] = { Wt[3 * NT * KPAD + o], Wt[3 * NT * KPAD + o + 4] };
#pragma unroll
                    for (int i = 0; i < 2; ++i) {
                        mma_tf32(accMu[i][j], ah[i], bmh);
                        mma_tf32(accMu[i][j], ah[i], bml);
                        mma_tf32(accMu[i][j], al[i], bmh);
                        mma_tf32(accSg[i][j], ah[i], bsh);
                        mma_tf32(accSg[i][j], ah[i], bsl);
                        mma_tf32(accSg[i][j], al[i], bsh);
                    }
                }
            }
            __syncthreads();
        }

        // epilogue: bias + exp/log/rcp + NLL partial sums
#pragma unroll
        for (int i = 0; i < 2; ++i) {
#pragma unroll
            for (int j = 0; j < 4; ++j) {
#pragma unroll
                for (int c = 0; c < 4; ++c) {
                    int h = n0 + wn * 32 + j * 8 + 2 * tg + (c & 1);
                    float m = accMu[i][j][c] + bias_s[h];
                    float v = expf(accSg[i][j][c] + bias_s[H + h]);
                    v = fmaxf(v, 1e-6f);        // GaussianNLLLoss eps clamp
                    float lg = logf(v);
                    float rc = 1.0f / v;
                    int slot = i * 2 + (c >> 1);
                    s1[slot] += lg;
                    s2[slot] += rc;
                    s3[slot] += m * rc;
                    s4[slot] += m * m * rc;
                }
            }
        }
    }

    // reduce over the 4 lanes of each group (cols), then across the 2 N-warps
#pragma unroll
    for (int slot = 0; slot < 4; ++slot) {
        s1[slot] += __shfl_xor_sync(0xffffffffu, s1[slot], 1);
        s1[slot] += __shfl_xor_sync(0xffffffffu, s1[slot], 2);
        s2[slot] += __shfl_xor_sync(0xffffffffu, s2[slot], 1);
        s2[slot] += __shfl_xor_sync(0xffffffffu, s2[slot], 2);
        s3[slot] += __shfl_xor_sync(0xffffffffu, s3[slot], 1);
        s3[slot] += __shfl_xor_sync(0xffffffffu, s3[slot], 2);
        s4[slot] += __shfl_xor_sync(0xffffffffu, s4[slot], 1);
        s4[slot] += __shfl_xor_sync(0xffffffffu, s4[slot], 2);
    }
    float (*red)[4] = (float(*)[4])(smem + SM_RED);
    __syncthreads();
    if (wn == 0 && tg == 0) {
#pragma unroll
        for (int slot = 0; slot < 4; ++slot) {
            int row = wm * 32 + (slot >> 1) * 16 + (slot & 1) * 8 + g;
            red[row][0] = s1[slot]; red[row][1] = s2[slot];
            red[row][2] = s3[slot]; red[row][3] = s4[slot];
        }
    }
    __syncthreads();
    if (wn == 1 && tg == 0) {
#pragma unroll
        for (int slot = 0; slot < 4; ++slot) {
            int row = wm * 32 + (slot >> 1) * 16 + (slot & 1) * 8 + g;
            int grow = r0 + row;
            if (grow < B) {
                g_coef[set][grow][0] = red[row][0] + s1[slot];
                g_coef[set][grow][1] = red[row][1] + s2[slot];
                g_coef[set][grow][2] = red[row][2] + s3[slot];
                g_coef[set][grow][3] = red[row][3] + s4[slot];
            }
        }
    }
}

// ---------------- Threefry-2x32-20 (exact JAX schedule) ----------------
__device__ __forceinline__ void threefry(uint32_t k0, uint32_t k1,
                                         uint32_t x0, uint32_t x1,
                                         uint32_t& o0, uint32_t& o1) {
    uint32_t ks2 = k0 ^ k1 ^ 0x1BD11BDAu;
    x0 += k0; x1 += k1;
#define TF_RND(r) { x0 += x1; x1 = (x1 << (r)) | (x1 >> (32 - (r))); x1 ^= x0; }
    TF_RND(13) TF_RND(15) TF_RND(26) TF_RND(6)
    x0 += k1;  x1 += ks2 + 1u;
    TF_RND(17) TF_RND(29) TF_RND(16) TF_RND(24)
    x0 += ks2; x1 += k0 + 2u;
    TF_RND(13) TF_RND(15) TF_RND(26) TF_RND(6)
    x0 += k0;  x1 += k1 + 3u;
    TF_RND(17) TF_RND(29) TF_RND(16) TF_RND(24)
    x0 += k1;  x1 += ks2 + 4u;
    TF_RND(13) TF_RND(15) TF_RND(26) TF_RND(6)
    x0 += ks2; x1 += k0 + 5u;
#undef TF_RND
    o0 = x0; o1 = x1;
}

__device__ __forceinline__ float bits_to_unit(uint32_t bits) {
    float f = __uint_as_float((bits >> 9) | 0x3f800000u) - 1.0f;
    return fmaxf(f, 0.0f);
}

// ---------------- per-row rejection sampling (JAX threefry, partitionable mode) ----------------
__global__ void sample_kernel(float* __restrict__ out, int B, float invH)
{
    int i = blockIdx.x * blockDim.x + threadIdx.x;
    if (i >= B) return;

    float s1x = g_coef[0][i][0], s2x = g_coef[0][i][1];
    float s3x = g_coef[0][i][2], s4x = g_coef[0][i][3];
    float s1y = g_coef[1][i][0], s2y = g_coef[1][i][1];
    float s3y = g_coef[1][i][2], s4y = g_coef[1][i][3];

    float ax = 0.5f * (s1x + s4x) * invH;
    float bxc = -s3x * invH;
    float cx = 0.5f * s2x * invH;
    float ay = 0.5f * (s1y + s4y) * invH;
    float byc = -s3y * invH;
    float cy = 0.5f * s2y * invH;

    uint32_t k0, k1;
    threefry(0u, 42u, 0u, (uint32_t)i, k0, k1);

    float xi = 0.0f;
    for (int it = 0; it < 4096; ++it) {
        uint32_t n0, n1, p0, p1, q0, q1;
        threefry(k0, k1, 0u, 0u, n0, n1);
        threefry(k0, k1, 0u, 1u, p0, p1);
        threefry(k0, k1, 0u, 2u, q0, q1);
        uint32_t ub0, ub1, xb0, xb1;
        threefry(p0, p1, 0u, 0u, ub0, ub1);
        threefry(q0, q1, 0u, 0u, xb0, xb1);
        float u  = bits_to_unit(ub0 ^ ub1);
        float x2 = bits_to_unit(xb0 ^ xb1);
        xi = 2.0f * x2 - 1.0f;

        float qx = fmaf(fmaf(cx, xi, bxc), xi, ax);
        float qy = fmaf(fmaf(cy, xi, byc), xi, ay);
        float q  = qx * qy;

        k0 = n0; k1 = n1;
        if (u >= q) break;
    }
    out[i] = fminf(fmaxf(xi, 1e-5f), 10.0f);
}

// ---------------- launch ----------------
extern "C" void kernel_launch(void* const* d_in, const int* in_sizes, int n_in,
                              void* d_out, int out_size)
{
    const float* x   = (const float*)d_in[0];
    const float* y   = (const float*)d_in[1];
    const float* Wmx = (const float*)d_in[2];
    const float* bmx = (const float*)d_in[3];
    const float* Wsx = (const float*)d_in[4];
    const float* bsx = (const float*)d_in[5];
    const float* Wmy = (const float*)d_in[6];
    const float* bmy = (const float*)d_in[7];
    const float* Wsy = (const float*)d_in[8];
    const float* bsy = (const float*)d_in[9];

    int H  = in_sizes[3];
    int IN = in_sizes[2] / H;
    int B  = in_sizes[0] / IN;

    int w4 = (H * IN) / 4;
    split_w_kernel<<<(w4 + 255) / 256, 256>>>(Wmx, 0, 0, w4);
    split_w_kernel<<<(w4 + 255) / 256, 256>>>(Wsx, 0, 1, w4);
    split_w_kernel<<<(w4 + 255) / 256, 256>>>(Wmy, 1, 0, w4);
    split_w_kernel<<<(w4 + 255) / 256, 256>>>(Wsy, 1, 1, w4);

    cudaFuncSetAttribute(coef_mma_kernel, cudaFuncAttributeMaxDynamicSharedMemorySize, SMEM_TOTAL);
    dim3 grid(B / MT, 2);
    coef_mma_kernel<<<grid, 256, SMEM_TOTAL>>>(x, y, bmx, bsx, bmy, bsy, B, IN, H);

    int thr = 256;
    sample_kernel<<<(B + thr - 1) / thr, thr>>>((float*)d_out, B, 1.0f / (float)H);
}